// round 1
// baseline (speedup 1.0000x reference)
#include <cuda_runtime.h>
#include <cstdint>

// Problem constants
#define BATCH 2
#define SEQ   2048
#define HDIM  1024
#define NHEAD 16
#define HD    64
#define MROWS (BATCH * SEQ)   // 4096

// ---------------- scratch buffers (device globals: allocation-free) ----------
__device__ float g_Q[MROWS * HDIM];
__device__ float g_K[MROWS * HDIM];
__device__ float g_V[MROWS * HDIM];
__device__ float g_AO[MROWS * HDIM];   // attention output
__device__ float g_Y[MROWS * HDIM];    // output projection result

// ---------------- SGEMM: C[M,N] = A[M,K] @ W[N,K]^T + bias[N] ----------------
// 128x128 tile, BK=8, 256 threads, 8x8 per-thread microtile.
__global__ void __launch_bounds__(256) sgemm_nt_bias(
    const float* __restrict__ A, const float* __restrict__ W,
    const float* __restrict__ bias, float* __restrict__ C,
    int M, int N, int K)
{
    __shared__ float As[8][128];
    __shared__ float Bs[8][128];

    const int tid = threadIdx.x;
    const int m0 = blockIdx.y * 128;
    const int n0 = blockIdx.x * 128;
    const int tm = (tid >> 4) * 8;      // 0..120
    const int tn = (tid & 15) * 8;      // 0..120

    const int lr = tid >> 1;            // 0..127
    const int lc = (tid & 1) * 4;       // 0 or 4

    const float* Aptr = A + (size_t)(m0 + lr) * K + lc;
    const float* Wptr = W + (size_t)(n0 + lr) * K + lc;

    float acc[8][8];
    #pragma unroll
    for (int i = 0; i < 8; i++)
        #pragma unroll
        for (int j = 0; j < 8; j++) acc[i][j] = 0.f;

    for (int k0 = 0; k0 < K; k0 += 8) {
        float4 a = *(const float4*)(Aptr + k0);
        float4 b = *(const float4*)(Wptr + k0);
        As[lc + 0][lr] = a.x; As[lc + 1][lr] = a.y;
        As[lc + 2][lr] = a.z; As[lc + 3][lr] = a.w;
        Bs[lc + 0][lr] = b.x; Bs[lc + 1][lr] = b.y;
        Bs[lc + 2][lr] = b.z; Bs[lc + 3][lr] = b.w;
        __syncthreads();

        #pragma unroll
        for (int k = 0; k < 8; k++) {
            float ra[8], rb[8];
            #pragma unroll
            for (int i = 0; i < 8; i++) ra[i] = As[k][tm + i];
            #pragma unroll
            for (int j = 0; j < 8; j++) rb[j] = Bs[k][tn + j];
            #pragma unroll
            for (int i = 0; i < 8; i++)
                #pragma unroll
                for (int j = 0; j < 8; j++)
                    acc[i][j] += ra[i] * rb[j];
        }
        __syncthreads();
    }

    #pragma unroll
    for (int i = 0; i < 8; i++) {
        float* crow = C + (size_t)(m0 + tm + i) * N + n0 + tn;
        #pragma unroll
        for (int j = 0; j < 8; j += 4) {
            float4 o;
            o.x = acc[i][j + 0] + bias[n0 + tn + j + 0];
            o.y = acc[i][j + 1] + bias[n0 + tn + j + 1];
            o.z = acc[i][j + 2] + bias[n0 + tn + j + 2];
            o.w = acc[i][j + 3] + bias[n0 + tn + j + 3];
            *(float4*)(crow + j) = o;
        }
    }
}

// ---------------- Flash attention (causal), 64x64 tiles, fp32 ---------------
// grid: (SEQ/64, NHEAD, BATCH), 256 threads (ty=tid/16 owns 4 q-rows,
// tx=tid%16 owns 4 cols/dims). Dynamic smem: Qs[64][64], Ks[64][65] (reused
// as P after score compute), Vs[64][64].
#define ATTN_SMEM_FLOATS (64*64 + 64*65 + 64*64)

__global__ void __launch_bounds__(256) attn_kernel(
    const float* __restrict__ Q, const float* __restrict__ K,
    const float* __restrict__ V, float* __restrict__ O)
{
    extern __shared__ float smem[];
    float* Qs = smem;               // [64][64]
    float* Ks = smem + 64 * 64;     // [64][65] (reused for P)
    float* Vs = Ks + 64 * 65;       // [64][64]

    const int tid = threadIdx.x;
    const int tx = tid & 15;
    const int ty = tid >> 4;
    const int rb = ty * 4;          // q-row base in tile
    const int db = tx * 4;          // col / dim base

    const int q0 = blockIdx.x * 64;
    const int h  = blockIdx.y;
    const int b  = blockIdx.z;
    const float scale = 0.125f;     // 1/sqrt(64)

    // Load scaled Q tile (coalesced float4)
    const float* Qg = Q + ((size_t)(b * SEQ + q0)) * HDIM + h * HD;
    #pragma unroll
    for (int l = 0; l < 4; l++) {
        int idx = tid + l * 256;
        int r  = idx >> 4;
        int c4 = (idx & 15) * 4;
        float4 v = *(const float4*)(Qg + (size_t)r * HDIM + c4);
        v.x *= scale; v.y *= scale; v.z *= scale; v.w *= scale;
        *(float4*)(Qs + r * 64 + c4) = v;
    }

    float m[4], lsum[4], acc[4][4];
    #pragma unroll
    for (int i = 0; i < 4; i++) {
        m[i] = -1e30f; lsum[i] = 0.f;
        #pragma unroll
        for (int j = 0; j < 4; j++) acc[i][j] = 0.f;
    }

    const int jmax = q0 / 64;
    for (int jt = 0; jt <= jmax; jt++) {
        const int k0 = jt * 64;
        const float* Kg = K + ((size_t)(b * SEQ + k0)) * HDIM + h * HD;
        const float* Vg = V + ((size_t)(b * SEQ + k0)) * HDIM + h * HD;

        __syncthreads();   // prev-iter consumers done (also covers Q load, iter 0)
        #pragma unroll
        for (int l = 0; l < 4; l++) {
            int idx = tid + l * 256;
            int r  = idx >> 4;
            int c4 = (idx & 15) * 4;
            float4 kv = *(const float4*)(Kg + (size_t)r * HDIM + c4);
            Ks[r * 65 + c4 + 0] = kv.x;
            Ks[r * 65 + c4 + 1] = kv.y;
            Ks[r * 65 + c4 + 2] = kv.z;
            Ks[r * 65 + c4 + 3] = kv.w;
            float4 vv = *(const float4*)(Vg + (size_t)r * HDIM + c4);
            *(float4*)(Vs + r * 64 + c4) = vv;
        }
        __syncthreads();

        // S = (Q*scale) @ K^T for this thread's 4x4 block
        float S[4][4];
        #pragma unroll
        for (int i = 0; i < 4; i++)
            #pragma unroll
            for (int j = 0; j < 4; j++) S[i][j] = 0.f;

        #pragma unroll 8
        for (int k = 0; k < 64; k++) {
            float qa[4], kb[4];
            #pragma unroll
            for (int i = 0; i < 4; i++) qa[i] = Qs[(rb + i) * 64 + k];
            #pragma unroll
            for (int j = 0; j < 4; j++) kb[j] = Ks[(db + j) * 65 + k];
            #pragma unroll
            for (int i = 0; i < 4; i++)
                #pragma unroll
                for (int j = 0; j < 4; j++)
                    S[i][j] += qa[i] * kb[j];
        }

        if (jt == jmax) {  // diagonal tile: mask k > q
            #pragma unroll
            for (int i = 0; i < 4; i++)
                #pragma unroll
                for (int j = 0; j < 4; j++)
                    if (k0 + db + j > q0 + rb + i) S[i][j] = -1e30f;
        }

        // Online softmax update per row
        float p[4][4];
        #pragma unroll
        for (int i = 0; i < 4; i++) {
            float rm = S[i][0];
            rm = fmaxf(rm, S[i][1]); rm = fmaxf(rm, S[i][2]); rm = fmaxf(rm, S[i][3]);
            #pragma unroll
            for (int off = 8; off > 0; off >>= 1)
                rm = fmaxf(rm, __shfl_xor_sync(0xffffffffu, rm, off, 16));
            float mn = fmaxf(m[i], rm);
            float al = __expf(m[i] - mn);
            m[i] = mn;
            float rs = 0.f;
            #pragma unroll
            for (int j = 0; j < 4; j++) {
                p[i][j] = __expf(S[i][j] - mn);
                rs += p[i][j];
            }
            #pragma unroll
            for (int off = 8; off > 0; off >>= 1)
                rs += __shfl_xor_sync(0xffffffffu, rs, off, 16);
            lsum[i] = lsum[i] * al + rs;
            #pragma unroll
            for (int j = 0; j < 4; j++) acc[i][j] *= al;
        }

        __syncthreads();   // everyone done reading Ks before overwriting with P
        #pragma unroll
        for (int i = 0; i < 4; i++)
            #pragma unroll
            for (int j = 0; j < 4; j++)
                Ks[(rb + i) * 65 + db + j] = p[i][j];
        __syncthreads();

        // acc += P @ V
        #pragma unroll 8
        for (int c = 0; c < 64; c++) {
            float4 vv = *(const float4*)(Vs + c * 64 + db);
            float pr[4];
            #pragma unroll
            for (int i = 0; i < 4; i++) pr[i] = Ks[(rb + i) * 65 + c];
            #pragma unroll
            for (int i = 0; i < 4; i++) {
                acc[i][0] += pr[i] * vv.x;
                acc[i][1] += pr[i] * vv.y;
                acc[i][2] += pr[i] * vv.z;
                acc[i][3] += pr[i] * vv.w;
            }
        }
    }

    // Normalize and write
    float* Og = O + ((size_t)(b * SEQ + q0 + rb)) * HDIM + h * HD + db;
    #pragma unroll
    for (int i = 0; i < 4; i++) {
        float inv = 1.f / lsum[i];
        float4 o;
        o.x = acc[i][0] * inv; o.y = acc[i][1] * inv;
        o.z = acc[i][2] * inv; o.w = acc[i][3] * inv;
        *(float4*)(Og + (size_t)i * HDIM) = o;
    }
}

// ---------------- Residual + LayerNorm: one block per row -------------------
__global__ void __launch_bounds__(256) ln_kernel(
    const float* __restrict__ X, const float* __restrict__ Y,
    const float* __restrict__ g, const float* __restrict__ be,
    float* __restrict__ out)
{
    const int row = blockIdx.x;
    const int tid = threadIdx.x;
    const float* xr = X + (size_t)row * HDIM;
    const float* yr = Y + (size_t)row * HDIM;

    float4 x4 = *(const float4*)(xr + tid * 4);
    float4 y4 = *(const float4*)(yr + tid * 4);
    float v0 = x4.x + y4.x, v1 = x4.y + y4.y, v2 = x4.z + y4.z, v3 = x4.w + y4.w;

    float s  = v0 + v1 + v2 + v3;
    float ss = v0 * v0 + v1 * v1 + v2 * v2 + v3 * v3;
    #pragma unroll
    for (int off = 16; off > 0; off >>= 1) {
        s  += __shfl_xor_sync(0xffffffffu, s, off);
        ss += __shfl_xor_sync(0xffffffffu, ss, off);
    }

    __shared__ float sbuf[8], ssbuf[8];
    __shared__ float mu_s, rstd_s;
    if ((tid & 31) == 0) { sbuf[tid >> 5] = s; ssbuf[tid >> 5] = ss; }
    __syncthreads();
    if (tid == 0) {
        float S = 0.f, SS = 0.f;
        #pragma unroll
        for (int k = 0; k < 8; k++) { S += sbuf[k]; SS += ssbuf[k]; }
        float mu = S * (1.0f / HDIM);
        float var = SS * (1.0f / HDIM) - mu * mu;
        mu_s = mu;
        rstd_s = rsqrtf(var + 1e-5f);
    }
    __syncthreads();
    float mu = mu_s, rs = rstd_s;

    float4 g4 = *(const float4*)(g + tid * 4);
    float4 b4 = *(const float4*)(be + tid * 4);
    float4 o;
    o.x = (v0 - mu) * rs * g4.x + b4.x;
    o.y = (v1 - mu) * rs * g4.y + b4.y;
    o.z = (v2 - mu) * rs * g4.z + b4.z;
    o.w = (v3 - mu) * rs * g4.w + b4.w;
    *(float4*)(out + (size_t)row * HDIM + tid * 4) = o;
}

// ---------------- launch ----------------------------------------------------
extern "C" void kernel_launch(void* const* d_in, const int* in_sizes, int n_in,
                              void* d_out, int out_size)
{
    const float* query = (const float*)d_in[0];
    const float* key   = (const float*)d_in[1];
    const float* value = (const float*)d_in[2];
    // d_in[3] = causal mask (pure tril, applied analytically)
    const float* Wq = (const float*)d_in[4];
    const float* bq = (const float*)d_in[5];
    const float* Wk = (const float*)d_in[6];
    const float* bk = (const float*)d_in[7];
    const float* Wv = (const float*)d_in[8];
    const float* bv = (const float*)d_in[9];
    const float* Wo = (const float*)d_in[10];
    const float* bo = (const float*)d_in[11];
    const float* lg = (const float*)d_in[12];
    const float* lb = (const float*)d_in[13];
    float* out = (float*)d_out;

    float *dQ, *dK, *dV, *dAO, *dY;
    cudaGetSymbolAddress((void**)&dQ,  g_Q);
    cudaGetSymbolAddress((void**)&dK,  g_K);
    cudaGetSymbolAddress((void**)&dV,  g_V);
    cudaGetSymbolAddress((void**)&dAO, g_AO);
    cudaGetSymbolAddress((void**)&dY,  g_Y);

    dim3 gGemm(HDIM / 128, MROWS / 128);  // (8, 32)
    sgemm_nt_bias<<<gGemm, 256>>>(query, Wq, bq, dQ, MROWS, HDIM, HDIM);
    sgemm_nt_bias<<<gGemm, 256>>>(key,   Wk, bk, dK, MROWS, HDIM, HDIM);
    sgemm_nt_bias<<<gGemm, 256>>>(value, Wv, bv, dV, MROWS, HDIM, HDIM);

    const int attn_smem = ATTN_SMEM_FLOATS * (int)sizeof(float);
    cudaFuncSetAttribute(attn_kernel, cudaFuncAttributeMaxDynamicSharedMemorySize,
                         attn_smem);
    attn_kernel<<<dim3(SEQ / 64, NHEAD, BATCH), 256, attn_smem>>>(dQ, dK, dV, dAO);

    sgemm_nt_bias<<<gGemm, 256>>>(dAO, Wo, bo, dY, MROWS, HDIM, HDIM);

    ln_kernel<<<MROWS, 256>>>(query, dY, lg, lb, out);
}

// round 2
// speedup vs baseline: 2.5547x; 2.5547x over previous
#include <cuda_runtime.h>
#include <cstdint>

#define BATCH 2
#define SEQ   2048
#define HDIM  1024
#define NHEAD 16
#define HD    64
#define MROWS (BATCH * SEQ)   // 4096

// ---------------- scratch (device globals: allocation-free) ------------------
__device__ float g_Q[MROWS * HDIM];
__device__ float g_K[MROWS * HDIM];
__device__ float g_V[MROWS * HDIM];
__device__ float g_AO[MROWS * HDIM];
__device__ float g_Y[MROWS * HDIM];

// ---------------- helpers ----------------------------------------------------
__device__ __forceinline__ uint32_t f2tf32(float x) {
    uint32_t u;
    asm("cvt.rna.tf32.f32 %0, %1;" : "=r"(u) : "f"(x));
    return u;
}

__device__ __forceinline__ void mma1688(float* c, const uint32_t* a, const uint32_t* b) {
    asm volatile(
        "mma.sync.aligned.m16n8k8.row.col.f32.tf32.tf32.f32 "
        "{%0,%1,%2,%3},{%4,%5,%6,%7},{%8,%9},{%0,%1,%2,%3};"
        : "+f"(c[0]), "+f"(c[1]), "+f"(c[2]), "+f"(c[3])
        : "r"(a[0]), "r"(a[1]), "r"(a[2]), "r"(a[3]), "r"(b[0]), "r"(b[1]));
}

// ---------------- TF32 tensor-core GEMM: C = A[M,K] @ W[N,K]^T + bias --------
// 128x128 tile, BK=32, 256 threads (8 warps, 2x4), warp tile 64x32.
#define GS 36   // smem row stride (36 % 32 == 4 -> conflict-free frag loads)

__global__ void __launch_bounds__(256) gemm_tc(
    const float* __restrict__ A, const float* __restrict__ W,
    const float* __restrict__ bias, float* __restrict__ C,
    int M, int N, int K)
{
    __shared__ uint32_t As[128 * GS];
    __shared__ uint32_t Bs[128 * GS];

    const int tid  = threadIdx.x;
    const int w    = tid >> 5;
    const int lane = tid & 31;
    const int g    = lane >> 2;
    const int t    = lane & 3;
    const int wm   = (w >> 2) * 64;   // 0 or 64
    const int wn   = (w & 3) * 32;    // 0..96

    const int m0 = blockIdx.y * 128;
    const int n0 = blockIdx.x * 128;

    const int lr = tid >> 3;          // 0..31
    const int lc = (tid & 7) * 4;     // 0..28

    const float* Ap = A + (size_t)(m0 + lr) * K + lc;
    const float* Wp = W + (size_t)(n0 + lr) * K + lc;

    float acc[4][4][4];
    #pragma unroll
    for (int i = 0; i < 4; i++)
        #pragma unroll
        for (int j = 0; j < 4; j++)
            #pragma unroll
            for (int r = 0; r < 4; r++) acc[i][j][r] = 0.f;

    float4 ra[4], rb[4];
    #pragma unroll
    for (int p = 0; p < 4; p++) {
        ra[p] = *(const float4*)(Ap + (size_t)p * 32 * K);
        rb[p] = *(const float4*)(Wp + (size_t)p * 32 * K);
    }

    const int niter = K / 32;
    for (int kb = 0; kb < niter; kb++) {
        // store prefetched regs to smem (tf32-converted)
        #pragma unroll
        for (int p = 0; p < 4; p++) {
            int row = lr + p * 32;
            uint32_t* pa = &As[row * GS + lc];
            pa[0] = f2tf32(ra[p].x); pa[1] = f2tf32(ra[p].y);
            pa[2] = f2tf32(ra[p].z); pa[3] = f2tf32(ra[p].w);
            uint32_t* pb = &Bs[row * GS + lc];
            pb[0] = f2tf32(rb[p].x); pb[1] = f2tf32(rb[p].y);
            pb[2] = f2tf32(rb[p].z); pb[3] = f2tf32(rb[p].w);
        }
        __syncthreads();

        if (kb + 1 < niter) {
            const float* Ap2 = Ap + (size_t)(kb + 1) * 32;
            const float* Wp2 = Wp + (size_t)(kb + 1) * 32;
            #pragma unroll
            for (int p = 0; p < 4; p++) {
                ra[p] = *(const float4*)(Ap2 + (size_t)p * 32 * K);
                rb[p] = *(const float4*)(Wp2 + (size_t)p * 32 * K);
            }
        }

        #pragma unroll
        for (int ks = 0; ks < 4; ks++) {
            const int k0 = ks * 8;
            uint32_t af[4][4], bf[4][2];
            #pragma unroll
            for (int mt = 0; mt < 4; mt++) {
                const int mb = wm + mt * 16;
                af[mt][0] = As[(mb + g) * GS + k0 + t];
                af[mt][1] = As[(mb + g + 8) * GS + k0 + t];
                af[mt][2] = As[(mb + g) * GS + k0 + t + 4];
                af[mt][3] = As[(mb + g + 8) * GS + k0 + t + 4];
            }
            #pragma unroll
            for (int nt = 0; nt < 4; nt++) {
                const int nb = wn + nt * 8;
                bf[nt][0] = Bs[(nb + g) * GS + k0 + t];
                bf[nt][1] = Bs[(nb + g) * GS + k0 + t + 4];
            }
            #pragma unroll
            for (int mt = 0; mt < 4; mt++)
                #pragma unroll
                for (int nt = 0; nt < 4; nt++)
                    mma1688(acc[mt][nt], af[mt], bf[nt]);
        }
        __syncthreads();
    }

    // epilogue with fused bias
    #pragma unroll
    for (int mt = 0; mt < 4; mt++) {
        const int row0 = m0 + wm + mt * 16 + g;
        const int row1 = row0 + 8;
        #pragma unroll
        for (int nt = 0; nt < 4; nt++) {
            const int col = n0 + wn + nt * 8 + t * 2;
            const float b0 = bias[col], b1 = bias[col + 1];
            float2 o0 = {acc[mt][nt][0] + b0, acc[mt][nt][1] + b1};
            float2 o1 = {acc[mt][nt][2] + b0, acc[mt][nt][3] + b1};
            *(float2*)(C + (size_t)row0 * N + col) = o0;
            *(float2*)(C + (size_t)row1 * N + col) = o1;
        }
    }
}

// ---------------- TF32 flash attention (causal), 64x64 tiles -----------------
#define AS 68  // smem row stride (68 % 32 == 4)
// smem: Qs[64*AS] Ks[64*AS] Vt[64*AS] Ss[64*AS] alphas[64] linv[64]
#define ATTN_SMEM_WORDS (4 * 64 * AS + 128)

__global__ void __launch_bounds__(256) attn_tc(
    const float* __restrict__ Q, const float* __restrict__ K,
    const float* __restrict__ V, float* __restrict__ O)
{
    extern __shared__ uint32_t sm[];
    uint32_t* Qs = sm;
    uint32_t* Ks = sm + 64 * AS;
    uint32_t* Vt = sm + 2 * 64 * AS;
    uint32_t* Ssu = sm + 3 * 64 * AS;
    float*    Ssf = (float*)Ssu;
    float*    alphas = (float*)(sm + 4 * 64 * AS);
    float*    linv   = alphas + 64;

    const int tid  = threadIdx.x;
    const int w    = tid >> 5;
    const int lane = tid & 31;
    const int g    = lane >> 2;
    const int t    = lane & 3;
    const int wq   = (w >> 1) * 16;    // q-row base (0,16,32,48)
    const int wn   = (w & 1) * 32;     // kcol base (S) / d base (PV)

    const int q0 = blockIdx.x * 64;
    const int h  = blockIdx.y;
    const int b  = blockIdx.z;
    const float scale = 0.125f;

    // load Q tile (scaled, tf32)
    const float* Qg = Q + ((size_t)(b * SEQ + q0)) * HDIM + h * HD;
    #pragma unroll
    for (int l = 0; l < 4; l++) {
        int idx = tid + l * 256;
        int r = idx >> 4;
        int c4 = (idx & 15) * 4;
        float4 v = *(const float4*)(Qg + (size_t)r * HDIM + c4);
        uint4 u;
        u.x = f2tf32(v.x * scale); u.y = f2tf32(v.y * scale);
        u.z = f2tf32(v.z * scale); u.w = f2tf32(v.w * scale);
        *(uint4*)(Qs + r * AS + c4) = u;
    }

    // softmax state: 4 threads per row, row = tid>>2
    const int srow = tid >> 2;
    const int seg  = tid & 3;
    float mrow = -1e30f, lrow = 0.f;

    float oacc[4][4];   // PV accum: 4 n-tiles (d), [c0,c1 row g | c2,c3 row g+8]
    #pragma unroll
    for (int nt = 0; nt < 4; nt++)
        #pragma unroll
        for (int r = 0; r < 4; r++) oacc[nt][r] = 0.f;

    const int jmax = blockIdx.x;
    for (int jt = 0; jt <= jmax; jt++) {
        const int k0g = jt * 64;
        const float* Kg = K + ((size_t)(b * SEQ + k0g)) * HDIM + h * HD;
        const float* Vg = V + ((size_t)(b * SEQ + k0g)) * HDIM + h * HD;

        __syncthreads();
        #pragma unroll
        for (int l = 0; l < 4; l++) {
            int idx = tid + l * 256;
            int r = idx >> 4;
            int c4 = (idx & 15) * 4;
            float4 kv = *(const float4*)(Kg + (size_t)r * HDIM + c4);
            uint4 u;
            u.x = f2tf32(kv.x); u.y = f2tf32(kv.y);
            u.z = f2tf32(kv.z); u.w = f2tf32(kv.w);
            *(uint4*)(Ks + r * AS + c4) = u;
            float4 vv = *(const float4*)(Vg + (size_t)r * HDIM + c4);
            Vt[(c4 + 0) * AS + r] = f2tf32(vv.x);
            Vt[(c4 + 1) * AS + r] = f2tf32(vv.y);
            Vt[(c4 + 2) * AS + r] = f2tf32(vv.z);
            Vt[(c4 + 3) * AS + r] = f2tf32(vv.w);
        }
        __syncthreads();

        // S = Q @ K^T (warp: rows wq..wq+15, cols wn..wn+31)
        float sacc[4][4];
        #pragma unroll
        for (int nt = 0; nt < 4; nt++)
            #pragma unroll
            for (int r = 0; r < 4; r++) sacc[nt][r] = 0.f;

        #pragma unroll
        for (int ks = 0; ks < 8; ks++) {
            const int k0 = ks * 8;
            uint32_t af[4];
            af[0] = Qs[(wq + g) * AS + k0 + t];
            af[1] = Qs[(wq + g + 8) * AS + k0 + t];
            af[2] = Qs[(wq + g) * AS + k0 + t + 4];
            af[3] = Qs[(wq + g + 8) * AS + k0 + t + 4];
            #pragma unroll
            for (int nt = 0; nt < 4; nt++) {
                uint32_t bfr[2];
                const int nb = wn + nt * 8;
                bfr[0] = Ks[(nb + g) * AS + k0 + t];
                bfr[1] = Ks[(nb + g) * AS + k0 + t + 4];
                mma1688(sacc[nt], af, bfr);
            }
        }

        // write S (fp32) to smem
        #pragma unroll
        for (int nt = 0; nt < 4; nt++) {
            const int col = wn + nt * 8 + t * 2;
            Ssf[(wq + g) * AS + col]     = sacc[nt][0];
            Ssf[(wq + g) * AS + col + 1] = sacc[nt][1];
            Ssf[(wq + g + 8) * AS + col]     = sacc[nt][2];
            Ssf[(wq + g + 8) * AS + col + 1] = sacc[nt][3];
        }
        __syncthreads();

        // online softmax: thread owns 16 cols of row srow
        float sv[16];
        {
            const int cb = seg * 16;
            #pragma unroll
            for (int j = 0; j < 4; j++) {
                float4 s4 = *(float4*)(Ssf + srow * AS + cb + j * 4);
                sv[j * 4 + 0] = s4.x; sv[j * 4 + 1] = s4.y;
                sv[j * 4 + 2] = s4.z; sv[j * 4 + 3] = s4.w;
            }
            if (jt == jmax) {
                #pragma unroll
                for (int j = 0; j < 16; j++)
                    if (k0g + cb + j > q0 + srow) sv[j] = -1e30f;
            }
            float tm = sv[0];
            #pragma unroll
            for (int j = 1; j < 16; j++) tm = fmaxf(tm, sv[j]);
            tm = fmaxf(tm, __shfl_xor_sync(0xffffffffu, tm, 1));
            tm = fmaxf(tm, __shfl_xor_sync(0xffffffffu, tm, 2));
            float mn = fmaxf(mrow, tm);
            float alpha = __expf(mrow - mn);
            mrow = mn;
            float rs = 0.f;
            #pragma unroll
            for (int j = 0; j < 16; j++) {
                sv[j] = __expf(sv[j] - mn);
                rs += sv[j];
            }
            rs += __shfl_xor_sync(0xffffffffu, rs, 1);
            rs += __shfl_xor_sync(0xffffffffu, rs, 2);
            lrow = lrow * alpha + rs;
            #pragma unroll
            for (int j = 0; j < 16; j++)
                Ssu[srow * AS + cb + j] = f2tf32(sv[j]);
            if (seg == 0) alphas[srow] = alpha;
        }
        __syncthreads();

        // PV: oacc = oacc*alpha + P @ V   (warp: rows wq.., d-cols wn..wn+31)
        const float al0 = alphas[wq + g];
        const float al1 = alphas[wq + g + 8];
        #pragma unroll
        for (int nt = 0; nt < 4; nt++) {
            oacc[nt][0] *= al0; oacc[nt][1] *= al0;
            oacc[nt][2] *= al1; oacc[nt][3] *= al1;
        }
        #pragma unroll
        for (int ks = 0; ks < 8; ks++) {
            const int k0 = ks * 8;
            uint32_t af[4];
            af[0] = Ssu[(wq + g) * AS + k0 + t];
            af[1] = Ssu[(wq + g + 8) * AS + k0 + t];
            af[2] = Ssu[(wq + g) * AS + k0 + t + 4];
            af[3] = Ssu[(wq + g + 8) * AS + k0 + t + 4];
            #pragma unroll
            for (int nt = 0; nt < 4; nt++) {
                uint32_t bfr[2];
                const int nb = wn + nt * 8;
                bfr[0] = Vt[(nb + g) * AS + k0 + t];
                bfr[1] = Vt[(nb + g) * AS + k0 + t + 4];
                mma1688(oacc[nt], af, bfr);
            }
        }
    }

    if (seg == 0) linv[srow] = 1.f / lrow;
    __syncthreads();

    const float il0 = linv[wq + g];
    const float il1 = linv[wq + g + 8];
    float* Og = O + ((size_t)(b * SEQ + q0)) * HDIM + h * HD;
    #pragma unroll
    for (int nt = 0; nt < 4; nt++) {
        const int col = wn + nt * 8 + t * 2;
        float2 o0 = {oacc[nt][0] * il0, oacc[nt][1] * il0};
        float2 o1 = {oacc[nt][2] * il1, oacc[nt][3] * il1};
        *(float2*)(Og + (size_t)(wq + g) * HDIM + col) = o0;
        *(float2*)(Og + (size_t)(wq + g + 8) * HDIM + col) = o1;
    }
}

// ---------------- Residual + LayerNorm ---------------------------------------
__global__ void __launch_bounds__(256) ln_kernel(
    const float* __restrict__ X, const float* __restrict__ Y,
    const float* __restrict__ g, const float* __restrict__ be,
    float* __restrict__ out)
{
    const int row = blockIdx.x;
    const int tid = threadIdx.x;
    const float* xr = X + (size_t)row * HDIM;
    const float* yr = Y + (size_t)row * HDIM;

    float4 x4 = *(const float4*)(xr + tid * 4);
    float4 y4 = *(const float4*)(yr + tid * 4);
    float v0 = x4.x + y4.x, v1 = x4.y + y4.y, v2 = x4.z + y4.z, v3 = x4.w + y4.w;

    float s  = v0 + v1 + v2 + v3;
    float ss = v0 * v0 + v1 * v1 + v2 * v2 + v3 * v3;
    #pragma unroll
    for (int off = 16; off > 0; off >>= 1) {
        s  += __shfl_xor_sync(0xffffffffu, s, off);
        ss += __shfl_xor_sync(0xffffffffu, ss, off);
    }

    __shared__ float sbuf[8], ssbuf[8];
    __shared__ float mu_s, rstd_s;
    if ((tid & 31) == 0) { sbuf[tid >> 5] = s; ssbuf[tid >> 5] = ss; }
    __syncthreads();
    if (tid == 0) {
        float S = 0.f, SS = 0.f;
        #pragma unroll
        for (int k = 0; k < 8; k++) { S += sbuf[k]; SS += ssbuf[k]; }
        float mu = S * (1.0f / HDIM);
        float var = SS * (1.0f / HDIM) - mu * mu;
        mu_s = mu;
        rstd_s = rsqrtf(var + 1e-5f);
    }
    __syncthreads();
    float mu = mu_s, rs = rstd_s;

    float4 g4 = *(const float4*)(g + tid * 4);
    float4 b4 = *(const float4*)(be + tid * 4);
    float4 o;
    o.x = (v0 - mu) * rs * g4.x + b4.x;
    o.y = (v1 - mu) * rs * g4.y + b4.y;
    o.z = (v2 - mu) * rs * g4.z + b4.z;
    o.w = (v3 - mu) * rs * g4.w + b4.w;
    *(float4*)(out + (size_t)row * HDIM + tid * 4) = o;
}

// ---------------- launch -----------------------------------------------------
extern "C" void kernel_launch(void* const* d_in, const int* in_sizes, int n_in,
                              void* d_out, int out_size)
{
    const float* query = (const float*)d_in[0];
    const float* key   = (const float*)d_in[1];
    const float* value = (const float*)d_in[2];
    const float* Wq = (const float*)d_in[4];
    const float* bq = (const float*)d_in[5];
    const float* Wk = (const float*)d_in[6];
    const float* bk = (const float*)d_in[7];
    const float* Wv = (const float*)d_in[8];
    const float* bv = (const float*)d_in[9];
    const float* Wo = (const float*)d_in[10];
    const float* bo = (const float*)d_in[11];
    const float* lg = (const float*)d_in[12];
    const float* lb = (const float*)d_in[13];
    float* out = (float*)d_out;

    float *dQ, *dK, *dV, *dAO, *dY;
    cudaGetSymbolAddress((void**)&dQ,  g_Q);
    cudaGetSymbolAddress((void**)&dK,  g_K);
    cudaGetSymbolAddress((void**)&dV,  g_V);
    cudaGetSymbolAddress((void**)&dAO, g_AO);
    cudaGetSymbolAddress((void**)&dY,  g_Y);

    dim3 gGemm(HDIM / 128, MROWS / 128);  // (8, 32)
    gemm_tc<<<gGemm, 256>>>(query, Wq, bq, dQ, MROWS, HDIM, HDIM);
    gemm_tc<<<gGemm, 256>>>(key,   Wk, bk, dK, MROWS, HDIM, HDIM);
    gemm_tc<<<gGemm, 256>>>(value, Wv, bv, dV, MROWS, HDIM, HDIM);

    const int attn_smem = ATTN_SMEM_WORDS * 4;
    cudaFuncSetAttribute(attn_tc, cudaFuncAttributeMaxDynamicSharedMemorySize,
                         attn_smem);
    attn_tc<<<dim3(SEQ / 64, NHEAD, BATCH), 256, attn_smem>>>(dQ, dK, dV, dAO);

    gemm_tc<<<gGemm, 256>>>(dAO, Wo, bo, dY, MROWS, HDIM, HDIM);

    ln_kernel<<<MROWS, 256>>>(query, dY, lg, lb, out);
}

// round 3
// speedup vs baseline: 4.0296x; 1.5773x over previous
#include <cuda_runtime.h>
#include <cuda_fp16.h>
#include <cstdint>

#define BATCH 2
#define SEQ   2048
#define HDIM  1024
#define NHEAD 16
#define HD    64
#define MROWS (BATCH * SEQ)   // 4096

// ---------------- scratch (device globals: allocation-free) ------------------
__device__ __half g_Qh[MROWS * HDIM];
__device__ __half g_Kh[MROWS * HDIM];
__device__ __half g_Vh[MROWS * HDIM];
__device__ float  g_AO[MROWS * HDIM];
__device__ float  g_Y[MROWS * HDIM];

// ---------------- helpers ----------------------------------------------------
__device__ __forceinline__ uint32_t f2tf32(float x) {
    uint32_t u;
    asm("cvt.rna.tf32.f32 %0, %1;" : "=r"(u) : "f"(x));
    return u;
}

__device__ __forceinline__ void mma1688(float* c, const uint32_t* a, const uint32_t* b) {
    asm volatile(
        "mma.sync.aligned.m16n8k8.row.col.f32.tf32.tf32.f32 "
        "{%0,%1,%2,%3},{%4,%5,%6,%7},{%8,%9},{%0,%1,%2,%3};"
        : "+f"(c[0]), "+f"(c[1]), "+f"(c[2]), "+f"(c[3])
        : "r"(a[0]), "r"(a[1]), "r"(a[2]), "r"(a[3]), "r"(b[0]), "r"(b[1]));
}

__device__ __forceinline__ void mma16816h(float* c, const uint32_t* a, const uint32_t* b) {
    asm volatile(
        "mma.sync.aligned.m16n8k16.row.col.f32.f16.f16.f32 "
        "{%0,%1,%2,%3},{%4,%5,%6,%7},{%8,%9},{%0,%1,%2,%3};"
        : "+f"(c[0]), "+f"(c[1]), "+f"(c[2]), "+f"(c[3])
        : "r"(a[0]), "r"(a[1]), "r"(a[2]), "r"(a[3]), "r"(b[0]), "r"(b[1]));
}

__device__ __forceinline__ void ldsm_x4(uint32_t& r0, uint32_t& r1, uint32_t& r2,
                                        uint32_t& r3, uint32_t addr) {
    asm volatile("ldmatrix.sync.aligned.m8n8.x4.shared.b16 {%0,%1,%2,%3}, [%4];"
                 : "=r"(r0), "=r"(r1), "=r"(r2), "=r"(r3) : "r"(addr));
}
__device__ __forceinline__ void ldsm_x4t(uint32_t& r0, uint32_t& r1, uint32_t& r2,
                                         uint32_t& r3, uint32_t addr) {
    asm volatile("ldmatrix.sync.aligned.m8n8.x4.trans.shared.b16 {%0,%1,%2,%3}, [%4];"
                 : "=r"(r0), "=r"(r1), "=r"(r2), "=r"(r3) : "r"(addr));
}

__device__ __forceinline__ void cp16(uint32_t dst, const void* src) {
    asm volatile("cp.async.cg.shared.global [%0], [%1], 16;" :: "r"(dst), "l"(src));
}
__device__ __forceinline__ void cp_commit_wait() {
    asm volatile("cp.async.commit_group;");
    asm volatile("cp.async.wait_group 0;");
}

// ---------------- TF32 tensor-core GEMM: C = A[M,K] @ W[N,K]^T + bias --------
#define GS 36

template <typename OutT>
__global__ void __launch_bounds__(256) gemm_tc(
    const float* __restrict__ A, const float* __restrict__ W,
    const float* __restrict__ bias, OutT* __restrict__ C,
    int M, int N, int K)
{
    __shared__ uint32_t As[128 * GS];
    __shared__ uint32_t Bs[128 * GS];

    const int tid  = threadIdx.x;
    const int w    = tid >> 5;
    const int lane = tid & 31;
    const int g    = lane >> 2;
    const int t    = lane & 3;
    const int wm   = (w >> 2) * 64;
    const int wn   = (w & 3) * 32;

    const int m0 = blockIdx.y * 128;
    const int n0 = blockIdx.x * 128;

    const int lr = tid >> 3;
    const int lc = (tid & 7) * 4;

    const float* Ap = A + (size_t)(m0 + lr) * K + lc;
    const float* Wp = W + (size_t)(n0 + lr) * K + lc;

    float acc[4][4][4];
    #pragma unroll
    for (int i = 0; i < 4; i++)
        #pragma unroll
        for (int j = 0; j < 4; j++)
            #pragma unroll
            for (int r = 0; r < 4; r++) acc[i][j][r] = 0.f;

    float4 ra[4], rb[4];
    #pragma unroll
    for (int p = 0; p < 4; p++) {
        ra[p] = *(const float4*)(Ap + (size_t)p * 32 * K);
        rb[p] = *(const float4*)(Wp + (size_t)p * 32 * K);
    }

    const int niter = K / 32;
    for (int kb = 0; kb < niter; kb++) {
        #pragma unroll
        for (int p = 0; p < 4; p++) {
            int row = lr + p * 32;
            uint32_t* pa = &As[row * GS + lc];
            pa[0] = f2tf32(ra[p].x); pa[1] = f2tf32(ra[p].y);
            pa[2] = f2tf32(ra[p].z); pa[3] = f2tf32(ra[p].w);
            uint32_t* pb = &Bs[row * GS + lc];
            pb[0] = f2tf32(rb[p].x); pb[1] = f2tf32(rb[p].y);
            pb[2] = f2tf32(rb[p].z); pb[3] = f2tf32(rb[p].w);
        }
        __syncthreads();

        if (kb + 1 < niter) {
            const float* Ap2 = Ap + (size_t)(kb + 1) * 32;
            const float* Wp2 = Wp + (size_t)(kb + 1) * 32;
            #pragma unroll
            for (int p = 0; p < 4; p++) {
                ra[p] = *(const float4*)(Ap2 + (size_t)p * 32 * K);
                rb[p] = *(const float4*)(Wp2 + (size_t)p * 32 * K);
            }
        }

        #pragma unroll
        for (int ks = 0; ks < 4; ks++) {
            const int k0 = ks * 8;
            uint32_t af[4][4], bf[4][2];
            #pragma unroll
            for (int mt = 0; mt < 4; mt++) {
                const int mb = wm + mt * 16;
                af[mt][0] = As[(mb + g) * GS + k0 + t];
                af[mt][1] = As[(mb + g + 8) * GS + k0 + t];
                af[mt][2] = As[(mb + g) * GS + k0 + t + 4];
                af[mt][3] = As[(mb + g + 8) * GS + k0 + t + 4];
            }
            #pragma unroll
            for (int nt = 0; nt < 4; nt++) {
                const int nb = wn + nt * 8;
                bf[nt][0] = Bs[(nb + g) * GS + k0 + t];
                bf[nt][1] = Bs[(nb + g) * GS + k0 + t + 4];
            }
            #pragma unroll
            for (int mt = 0; mt < 4; mt++)
                #pragma unroll
                for (int nt = 0; nt < 4; nt++)
                    mma1688(acc[mt][nt], af[mt], bf[nt]);
        }
        __syncthreads();
    }

    #pragma unroll
    for (int mt = 0; mt < 4; mt++) {
        const int row0 = m0 + wm + mt * 16 + g;
        const int row1 = row0 + 8;
        #pragma unroll
        for (int nt = 0; nt < 4; nt++) {
            const int col = n0 + wn + nt * 8 + t * 2;
            const float b0 = bias[col], b1 = bias[col + 1];
            float c00 = acc[mt][nt][0] + b0, c01 = acc[mt][nt][1] + b1;
            float c10 = acc[mt][nt][2] + b0, c11 = acc[mt][nt][3] + b1;
            if constexpr (sizeof(OutT) == 4) {
                *(float2*)((float*)C + (size_t)row0 * N + col) = make_float2(c00, c01);
                *(float2*)((float*)C + (size_t)row1 * N + col) = make_float2(c10, c11);
            } else {
                *(__half2*)((__half*)C + (size_t)row0 * N + col) = __floats2half2_rn(c00, c01);
                *(__half2*)((__half*)C + (size_t)row1 * N + col) = __floats2half2_rn(c10, c11);
            }
        }
    }
}

// ---------------- FA2-style fp16 flash attention (causal) --------------------
// Block: 128 q-rows (8 warps x 16 rows), K-tile 64. S and P live in registers.
#define KS_STR 72   // halves per smem row (144B: 16B-aligned, conflict-free ldsm)

__global__ void __launch_bounds__(256) attn_fa(
    const __half* __restrict__ Qh, const __half* __restrict__ Kh,
    const __half* __restrict__ Vh, float* __restrict__ O)
{
    __shared__ __half Ks[64 * KS_STR];
    __shared__ __half Vs[64 * KS_STR];

    const int tid  = threadIdx.x;
    const int w    = tid >> 5;
    const int lane = tid & 31;
    const int g    = lane >> 2;
    const int t    = lane & 3;
    const int wq   = w * 16;

    const int q0 = (gridDim.x - 1 - blockIdx.x) * 128;  // heavy blocks first
    const int h  = blockIdx.y;
    const int b  = blockIdx.z;

    const uint32_t ks_base = (uint32_t)__cvta_generic_to_shared(Ks);
    const uint32_t vs_base = (uint32_t)__cvta_generic_to_shared(Vs);

    // ---- stage Q tile [128][64] into (Ks|Vs) region, ldmatrix into regs ----
    const __half* Qg = Qh + ((size_t)(b * SEQ + q0)) * HDIM + h * HD;
    {
        #pragma unroll
        for (int j = 0; j < 4; j++) {
            int i = tid + j * 256;          // 0..1023 chunks of 8 halves
            int r = i >> 3;
            int c8 = (i & 7) * 8;
            cp16(ks_base + (r * KS_STR + c8) * 2, Qg + (size_t)r * HDIM + c8);
        }
        cp_commit_wait();
        __syncthreads();
    }

    uint32_t qf[4][4];  // 4 k-steps of A fragments (scaled by 1/8)
    {
        const __half2 sc = __half2half2(__float2half(0.125f));
        const int row = wq + (lane & 15);
        const int chi = (lane >> 4) * 8;
        #pragma unroll
        for (int ks = 0; ks < 4; ks++) {
            uint32_t addr = ks_base + (row * KS_STR + ks * 16 + chi) * 2;
            ldsm_x4(qf[ks][0], qf[ks][1], qf[ks][2], qf[ks][3], addr);
            #pragma unroll
            for (int r = 0; r < 4; r++) {
                __half2 v = *(__half2*)&qf[ks][r];
                v = __hmul2(v, sc);
                qf[ks][r] = *(uint32_t*)&v;
            }
        }
    }

    float m0r = -1e30f, m1r = -1e30f, l0r = 0.f, l1r = 0.f;
    float oacc[8][4];
    #pragma unroll
    for (int j = 0; j < 8; j++)
        #pragma unroll
        for (int r = 0; r < 4; r++) oacc[j][r] = 0.f;

    // ldmatrix lane addresses (precomputed components)
    const int kn_row = (lane & 7) + ((lane >> 4) & 1) * 8;   // K: n-row within 16-group
    const int kn_col = ((lane >> 3) & 1) * 8;                // K: k-col offset
    const int vk_row = (lane & 7) + ((lane >> 3) & 1) * 8;   // V: k-row within 16-step
    const int vn_col = (lane >> 4) * 8;                      // V: n-col offset

    const int jmax = (q0 + 127) / 64;
    for (int jt = 0; jt <= jmax; jt++) {
        const int k0g = jt * 64;
        const __half* Kg = Kh + ((size_t)(b * SEQ + k0g)) * HDIM + h * HD;
        const __half* Vg = Vh + ((size_t)(b * SEQ + k0g)) * HDIM + h * HD;

        __syncthreads();
        #pragma unroll
        for (int j = 0; j < 2; j++) {
            int i = tid + j * 256;          // 0..511 chunks
            int r = i >> 3;
            int c8 = (i & 7) * 8;
            cp16(ks_base + (r * KS_STR + c8) * 2, Kg + (size_t)r * HDIM + c8);
            cp16(vs_base + (r * KS_STR + c8) * 2, Vg + (size_t)r * HDIM + c8);
        }
        cp_commit_wait();
        __syncthreads();

        const bool active = (k0g <= q0 + wq + 15);
        if (active) {
            // ---- S = Q @ K^T : sacc[8 n-tiles][4] --------------------------
            float sacc[8][4];
            #pragma unroll
            for (int j = 0; j < 8; j++)
                #pragma unroll
                for (int r = 0; r < 4; r++) sacc[j][r] = 0.f;

            #pragma unroll
            for (int ks = 0; ks < 4; ks++) {
                #pragma unroll
                for (int ng = 0; ng < 4; ng++) {
                    uint32_t b0, b1, b2, b3;
                    uint32_t addr = ks_base +
                        ((ng * 16 + kn_row) * KS_STR + ks * 16 + kn_col) * 2;
                    ldsm_x4(b0, b1, b2, b3, addr);
                    uint32_t bf0[2] = {b0, b1}, bf1[2] = {b2, b3};
                    mma16816h(sacc[ng * 2],     qf[ks], bf0);
                    mma16816h(sacc[ng * 2 + 1], qf[ks], bf1);
                }
            }

            // ---- causal mask (only near diagonal) --------------------------
            if (k0g + 63 > q0 + wq) {
                const int row0 = q0 + wq + g;
                const int row1 = row0 + 8;
                #pragma unroll
                for (int j = 0; j < 8; j++) {
                    const int col = k0g + j * 8 + t * 2;
                    if (col > row0)     sacc[j][0] = -1e30f;
                    if (col + 1 > row0) sacc[j][1] = -1e30f;
                    if (col > row1)     sacc[j][2] = -1e30f;
                    if (col + 1 > row1) sacc[j][3] = -1e30f;
                }
            }

            // ---- online softmax (register + quad shuffle) ------------------
            float tm0 = -1e30f, tm1 = -1e30f;
            #pragma unroll
            for (int j = 0; j < 8; j++) {
                tm0 = fmaxf(tm0, fmaxf(sacc[j][0], sacc[j][1]));
                tm1 = fmaxf(tm1, fmaxf(sacc[j][2], sacc[j][3]));
            }
            tm0 = fmaxf(tm0, __shfl_xor_sync(0xffffffffu, tm0, 1));
            tm0 = fmaxf(tm0, __shfl_xor_sync(0xffffffffu, tm0, 2));
            tm1 = fmaxf(tm1, __shfl_xor_sync(0xffffffffu, tm1, 1));
            tm1 = fmaxf(tm1, __shfl_xor_sync(0xffffffffu, tm1, 2));

            const float mn0 = fmaxf(m0r, tm0);
            const float mn1 = fmaxf(m1r, tm1);
            const float al0 = __expf(m0r - mn0);
            const float al1 = __expf(m1r - mn1);
            m0r = mn0; m1r = mn1;

            float rs0 = 0.f, rs1 = 0.f;
            #pragma unroll
            for (int j = 0; j < 8; j++) {
                sacc[j][0] = __expf(sacc[j][0] - mn0);
                sacc[j][1] = __expf(sacc[j][1] - mn0);
                sacc[j][2] = __expf(sacc[j][2] - mn1);
                sacc[j][3] = __expf(sacc[j][3] - mn1);
                rs0 += sacc[j][0] + sacc[j][1];
                rs1 += sacc[j][2] + sacc[j][3];
            }
            rs0 += __shfl_xor_sync(0xffffffffu, rs0, 1);
            rs0 += __shfl_xor_sync(0xffffffffu, rs0, 2);
            rs1 += __shfl_xor_sync(0xffffffffu, rs1, 1);
            rs1 += __shfl_xor_sync(0xffffffffu, rs1, 2);
            l0r = l0r * al0 + rs0;
            l1r = l1r * al1 + rs1;

            // ---- P fragments (half2 pack, direct A-layout) -----------------
            uint32_t pa[4][4];
            #pragma unroll
            for (int ks = 0; ks < 4; ks++) {
                __half2 h0 = __floats2half2_rn(sacc[2*ks][0],   sacc[2*ks][1]);
                __half2 h1 = __floats2half2_rn(sacc[2*ks][2],   sacc[2*ks][3]);
                __half2 h2 = __floats2half2_rn(sacc[2*ks+1][0], sacc[2*ks+1][1]);
                __half2 h3 = __floats2half2_rn(sacc[2*ks+1][2], sacc[2*ks+1][3]);
                pa[ks][0] = *(uint32_t*)&h0; pa[ks][1] = *(uint32_t*)&h1;
                pa[ks][2] = *(uint32_t*)&h2; pa[ks][3] = *(uint32_t*)&h3;
            }

            // ---- rescale O, then O += P @ V -------------------------------
            #pragma unroll
            for (int j = 0; j < 8; j++) {
                oacc[j][0] *= al0; oacc[j][1] *= al0;
                oacc[j][2] *= al1; oacc[j][3] *= al1;
            }
            #pragma unroll
            for (int ks = 0; ks < 4; ks++) {
                #pragma unroll
                for (int ng = 0; ng < 4; ng++) {
                    uint32_t b0, b1, b2, b3;
                    uint32_t addr = vs_base +
                        ((ks * 16 + vk_row) * KS_STR + ng * 16 + vn_col) * 2;
                    ldsm_x4t(b0, b1, b2, b3, addr);
                    uint32_t bf0[2] = {b0, b1}, bf1[2] = {b2, b3};
                    mma16816h(oacc[ng * 2],     pa[ks], bf0);
                    mma16816h(oacc[ng * 2 + 1], pa[ks], bf1);
                }
            }
        }
    }

    // ---- normalize + write --------------------------------------------------
    const float il0 = 1.f / l0r;
    const float il1 = 1.f / l1r;
    float* Og = O + ((size_t)(b * SEQ + q0 + wq)) * HDIM + h * HD;
    #pragma unroll
    for (int j = 0; j < 8; j++) {
        const int col = j * 8 + t * 2;
        *(float2*)(Og + (size_t)g * HDIM + col) =
            make_float2(oacc[j][0] * il0, oacc[j][1] * il0);
        *(float2*)(Og + (size_t)(g + 8) * HDIM + col) =
            make_float2(oacc[j][2] * il1, oacc[j][3] * il1);
    }
}

// ---------------- Residual + LayerNorm ---------------------------------------
__global__ void __launch_bounds__(256) ln_kernel(
    const float* __restrict__ X, const float* __restrict__ Y,
    const float* __restrict__ g, const float* __restrict__ be,
    float* __restrict__ out)
{
    const int row = blockIdx.x;
    const int tid = threadIdx.x;
    const float* xr = X + (size_t)row * HDIM;
    const float* yr = Y + (size_t)row * HDIM;

    float4 x4 = *(const float4*)(xr + tid * 4);
    float4 y4 = *(const float4*)(yr + tid * 4);
    float v0 = x4.x + y4.x, v1 = x4.y + y4.y, v2 = x4.z + y4.z, v3 = x4.w + y4.w;

    float s  = v0 + v1 + v2 + v3;
    float ss = v0 * v0 + v1 * v1 + v2 * v2 + v3 * v3;
    #pragma unroll
    for (int off = 16; off > 0; off >>= 1) {
        s  += __shfl_xor_sync(0xffffffffu, s, off);
        ss += __shfl_xor_sync(0xffffffffu, ss, off);
    }

    __shared__ float sbuf[8], ssbuf[8];
    __shared__ float mu_s, rstd_s;
    if ((tid & 31) == 0) { sbuf[tid >> 5] = s; ssbuf[tid >> 5] = ss; }
    __syncthreads();
    if (tid == 0) {
        float S = 0.f, SS = 0.f;
        #pragma unroll
        for (int k = 0; k < 8; k++) { S += sbuf[k]; SS += ssbuf[k]; }
        float mu = S * (1.0f / HDIM);
        float var = SS * (1.0f / HDIM) - mu * mu;
        mu_s = mu;
        rstd_s = rsqrtf(var + 1e-5f);
    }
    __syncthreads();
    float mu = mu_s, rs = rstd_s;

    float4 g4 = *(const float4*)(g + tid * 4);
    float4 b4 = *(const float4*)(be + tid * 4);
    float4 o;
    o.x = (v0 - mu) * rs * g4.x + b4.x;
    o.y = (v1 - mu) * rs * g4.y + b4.y;
    o.z = (v2 - mu) * rs * g4.z + b4.z;
    o.w = (v3 - mu) * rs * g4.w + b4.w;
    *(float4*)(out + (size_t)row * HDIM + tid * 4) = o;
}

// ---------------- launch -----------------------------------------------------
extern "C" void kernel_launch(void* const* d_in, const int* in_sizes, int n_in,
                              void* d_out, int out_size)
{
    const float* query = (const float*)d_in[0];
    const float* key   = (const float*)d_in[1];
    const float* value = (const float*)d_in[2];
    const float* Wq = (const float*)d_in[4];
    const float* bq = (const float*)d_in[5];
    const float* Wk = (const float*)d_in[6];
    const float* bk = (const float*)d_in[7];
    const float* Wv = (const float*)d_in[8];
    const float* bv = (const float*)d_in[9];
    const float* Wo = (const float*)d_in[10];
    const float* bo = (const float*)d_in[11];
    const float* lg = (const float*)d_in[12];
    const float* lb = (const float*)d_in[13];
    float* out = (float*)d_out;

    __half *dQh, *dKh, *dVh;
    float *dAO, *dY;
    cudaGetSymbolAddress((void**)&dQh, g_Qh);
    cudaGetSymbolAddress((void**)&dKh, g_Kh);
    cudaGetSymbolAddress((void**)&dVh, g_Vh);
    cudaGetSymbolAddress((void**)&dAO, g_AO);
    cudaGetSymbolAddress((void**)&dY,  g_Y);

    dim3 gGemm(HDIM / 128, MROWS / 128);
    gemm_tc<__half><<<gGemm, 256>>>(query, Wq, bq, dQh, MROWS, HDIM, HDIM);
    gemm_tc<__half><<<gGemm, 256>>>(key,   Wk, bk, dKh, MROWS, HDIM, HDIM);
    gemm_tc<__half><<<gGemm, 256>>>(value, Wv, bv, dVh, MROWS, HDIM, HDIM);

    attn_fa<<<dim3(SEQ / 128, NHEAD, BATCH), 256>>>(dQh, dKh, dVh, dAO);

    gemm_tc<float><<<gGemm, 256>>>(dAO, Wo, bo, dY, MROWS, HDIM, HDIM);

    ln_kernel<<<MROWS, 256>>>(query, dY, lg, lb, out);
}